// round 12
// baseline (speedup 1.0000x reference)
#include <cuda_runtime.h>

// out[n, c, k] = sum_h g(pre[n,h]) * W1[k,h] * W2[h,c],  g = 1 - tanh^2
// pre[n,h] = b1[h] + pos[n]·W1[:,h]
//
// out[n, m] = sum_h g[n,h] * M[h,m],  m = c*3+k,  M[h,m] = W2[h,c]*W1[k,h].
// CTA: 64 nodes, 128 threads. Thread = 4 nodes x 12 output cols (48 fp32 accs).
// Per h: 2 LDS.128 (duplicated g pairs, 4 nodes) + 3 LDS.128 (12-col M slice)
//        -> 24 FFMA2, zero mov overhead.
// CH=32 chunks keep smem ~33 KB -> 5 CTAs/SM (reg-limited).

#define NN   50000
#define HH   256
#define CC   32
#define MOUT 96
#define CH   32     // h per chunk
#define NPC  64     // nodes per CTA
#define TPB  128
#define RN   4      // nodes per thread
#define MSL  12     // output columns per thread

__global__ __launch_bounds__(TPB, 5)
void grad_kernel(const float* __restrict__ pos,
                 const float* __restrict__ W1,   // [3, H]
                 const float* __restrict__ b1,   // [H]
                 const float* __restrict__ W2,   // [H, C]
                 float* __restrict__ out)        // [N, C, 3]
{
    __shared__ float4 ws4[HH];                         // {b1, W1x, W1y, W1z} (4 KB)
    __shared__ float  pxs[NPC], pys[NPC], pzs[NPC];
    __shared__ __align__(16) float Ms[CH * MOUT];      // M chunk (12 KB)
    __shared__ __align__(16) float gs2[CH * NPC * 2];  // {g,g} pairs (16 KB)

    const int tid = threadIdx.x;
    const int blk = blockIdx.x;
    const int slc = tid & 7;        // column slice (12 cols)
    const int ng  = tid >> 3;       // node group (4 nodes), 0..15
    const int n0  = blk * NPC + ng * RN;

    // ---- one-time setup ----
    for (int i = tid; i < HH; i += TPB)
        ws4[i] = make_float4(b1[i], W1[i], W1[HH + i], W1[2 * HH + i]);
    for (int i = tid; i < 3 * NPC; i += TPB) {
        int gidx = blk * 3 * NPC + i;                  // pos is [N,3] packed
        float v  = (gidx < 3 * NN) ? pos[gidx] : 0.f;
        int pn = i / 3, comp = i - 3 * pn;
        if      (comp == 0) pxs[pn] = v;
        else if (comp == 1) pys[pn] = v;
        else                pzs[pn] = v;
    }
    __syncthreads();

    // 4 nodes x 12 cols accumulators as 4 x 6 packed b64
    unsigned long long acc[RN][6];
#pragma unroll
    for (int r = 0; r < RN; ++r)
#pragma unroll
        for (int j = 0; j < 6; ++j) acc[r][j] = 0ull;

    // phase-1 mapping: thread -> (node, 16-h half); 16 (h,node) values each
    const int p1n  = tid & 63;
    const int p1hi = tid >> 6;      // 0 or 1
    const float ppx = pxs[p1n], ppy = pys[p1n], ppz = pzs[p1n];

    // M-build mapping: thread (tid<96) owns output column m = tid
    const int mc = tid / 3;          // channel c
    const int mk = tid - 3 * mc;     // spatial k

    for (int h0 = 0; h0 < HH; h0 += CH) {
        // build M chunk: column-per-thread, div-free inner loop
        if (tid < MOUT) {
            const float* w2c = W2 + (size_t)h0 * CC + mc;   // stride CC per h
            const float* w1k = W1 + mk * HH + h0;
#pragma unroll 4
            for (int h = 0; h < CH; ++h)
                Ms[h * MOUT + tid] = w2c[h * CC] * w1k[h];
        }

        // phase 1: stage duplicated g pairs for 32 h x 64 nodes
#pragma unroll 4
        for (int i = 0; i < 16; ++i) {
            int    h   = p1hi * 16 + i;
            float4 w   = ws4[h0 + h];                       // warp-uniform
            float  pre = fmaf(ppx, w.y, fmaf(ppy, w.z, fmaf(ppz, w.w, w.x)));
            // g = 1 - tanh^2 = s*(2-s), s = 2/(e^{2x}+1); overflow-safe
            float  u   = __expf(pre + pre);
            float  s   = __fdividef(2.0f, u + 1.0f);
            float  g   = s * (2.0f - s);
            reinterpret_cast<float2*>(gs2)[h * NPC + p1n] = make_float2(g, g);
        }
        __syncthreads();

        // phase 2: 24 FFMA2 per h per thread, no movs
#pragma unroll 4
        for (int h = 0; h < CH; ++h) {
            // duplicated g for 4 nodes: 2 LDS.128, broadcast, conflict-free
            const ulonglong2* Gp =
                reinterpret_cast<const ulonglong2*>(&gs2[(h * NPC + ng * RN) * 2]);
            ulonglong2 ga = Gp[0];      // {g0,g0},{g1,g1}
            ulonglong2 gb = Gp[1];      // {g2,g2},{g3,g3}

            // 12-col M slice: 3 LDS.128, conflict-free (48B stride)
            const ulonglong2* Mrow =
                reinterpret_cast<const ulonglong2*>(&Ms[h * MOUT + slc * MSL]);
            ulonglong2 m0 = Mrow[0], m1 = Mrow[1], m2 = Mrow[2];

            unsigned long long g2v[RN] = { ga.x, ga.y, gb.x, gb.y };
#pragma unroll
            for (int r = 0; r < RN; ++r) {
                asm("fma.rn.f32x2 %0, %1, %2, %0;" : "+l"(acc[r][0]) : "l"(g2v[r]), "l"(m0.x));
                asm("fma.rn.f32x2 %0, %1, %2, %0;" : "+l"(acc[r][1]) : "l"(g2v[r]), "l"(m0.y));
                asm("fma.rn.f32x2 %0, %1, %2, %0;" : "+l"(acc[r][2]) : "l"(g2v[r]), "l"(m1.x));
                asm("fma.rn.f32x2 %0, %1, %2, %0;" : "+l"(acc[r][3]) : "l"(g2v[r]), "l"(m1.y));
                asm("fma.rn.f32x2 %0, %1, %2, %0;" : "+l"(acc[r][4]) : "l"(g2v[r]), "l"(m2.x));
                asm("fma.rn.f32x2 %0, %1, %2, %0;" : "+l"(acc[r][5]) : "l"(g2v[r]), "l"(m2.y));
            }
        }
        __syncthreads();            // protect Ms/gs2 before next chunk
    }

    // store: 3 STG.128 per node (12 cols, 16B-aligned: slc*48B)
#pragma unroll
    for (int r = 0; r < RN; ++r) {
        int n = n0 + r;
        if (n < NN) {
            float4* o4 = reinterpret_cast<float4*>(out + (size_t)n * MOUT + slc * MSL);
#pragma unroll
            for (int j = 0; j < 3; ++j) {
                float4 o;
                asm("mov.b64 {%0, %1}, %2;" : "=f"(o.x), "=f"(o.y) : "l"(acc[r][2 * j]));
                asm("mov.b64 {%0, %1}, %2;" : "=f"(o.z), "=f"(o.w) : "l"(acc[r][2 * j + 1]));
                o4[j] = o;
            }
        }
    }
}

extern "C" void kernel_launch(void* const* d_in, const int* in_sizes, int n_in,
                              void* d_out, int out_size)
{
    const float* pos = (const float*)d_in[0];  // [N,3]
    const float* W1  = (const float*)d_in[1];  // [3,H]
    const float* b1  = (const float*)d_in[2];  // [H]
    const float* W2  = (const float*)d_in[3];  // [H,C]
    float* out = (float*)d_out;                // [N,C,3] fp32

    int grid = (NN + NPC - 1) / NPC;           // 782 CTAs
    grad_kernel<<<grid, TPB>>>(pos, W1, b1, W2, out);
}